// round 12
// baseline (speedup 1.0000x reference)
#include <cuda_runtime.h>
#include <cuda_fp16.h>
#include <math.h>
#include <stdint.h>

#define N_  10000
#define E_  20000
#define B_  400
#define ND_ 32
#define ED_ 16
#define D_  64
#define DD_ 4096   // D*D

// ---------------- scratch (device globals; no cudaMalloc allowed) ----------------
__device__ float g_h[N_ * D_];            // node hidden / out (fp32)
__device__ __half g_rh[E_ * D_];          // edge MLP hidden, fp16
__device__ __half g_w3[65 * DD_];         // permuted W_e2 [k][f][d] (+ chunk 64 = b2^T)
__device__ float g_agg[3 * N_ * D_];      // scatter accumulators (one per iteration)
__device__ float g_cnt[N_];               // dst degree
__device__ int   g_src[E_], g_dst[E_], g_batch[N_];
__device__ int   g_gcnt[B_];
__device__ int   g_ptr[B_ + 1];
__device__ float g_qstar[B_ * 2 * D_];
__device__ float g_hl[B_ * D_];
__device__ float g_cl[B_ * D_];
__device__ float g_e[N_];                 // per-node attention logits / weights

__device__ __forceinline__ float sigm(float x) { return 1.f / (1.f + expf(-x)); }

__device__ __forceinline__ uint32_t smem_u32(const void* p) {
    uint32_t a;
    asm("{ .reg .u64 t; cvta.to.shared.u64 t, %1; cvt.u32.u64 %0, t; }" : "=r"(a) : "l"(p));
    return a;
}
__device__ __forceinline__ void cp16(uint32_t dst, const void* src) {
    asm volatile("cp.async.cg.shared.global [%0], [%1], 16;" :: "r"(dst), "l"(src));
}

// ---------------- prep: encoders + W3 build + zero init (launch #1) ----------------
__global__ void prep_kernel(const float* __restrict__ x,
                            const float* __restrict__ W_in, const float* __restrict__ b_in,
                            const float* __restrict__ ea,
                            const float* __restrict__ W_e1, const float* __restrict__ b_e1,
                            const float* __restrict__ W_e2, const float* __restrict__ b_e2) {
    int i = blockIdx.x * blockDim.x + threadIdx.x;
    // encoders
    if (i < N_ * D_) {
        int n = i >> 6, f = i & 63;
        float acc = b_in[f];
        const float* xr = x + n * ND_;
        const float* wr = W_in + f * ND_;
#pragma unroll
        for (int k = 0; k < ND_; k++) acc += xr[k] * wr[k];
        g_h[i] = fmaxf(acc, 0.f);
    } else if (i < N_ * D_ + E_ * D_) {
        int j = i - N_ * D_;
        int e = j >> 6, f = j & 63;
        float acc = b_e1[f];
        const float* er = ea + e * ED_;
        const float* wr = W_e1 + f * ED_;
#pragma unroll
        for (int k = 0; k < ED_; k++) acc += er[k] * wr[k];
        g_rh[j] = __float2half(fmaxf(acc, 0.f));
    }
    // W3 permute: w3[k][f][d] = W_e2[(d*64+f)*64 + k]; chunk 64 = b2 transposed
    if (i < 65 * DD_) {
        int k = i >> 12, rem = i & 4095;
        int f = rem >> 6, d = rem & 63;
        float v = (k < 64) ? W_e2[(d * 64 + f) * 64 + k] : b_e2[d * 64 + f];
        g_w3[i] = __float2half(v);
    }
    // zero accumulators (grid == 3*N_*D_ == 1.92M exactly)
    if (i < 3 * N_ * D_) g_agg[i] = 0.f;
    if (i < N_) g_cnt[i] = 0.f;
    if (i < B_) g_gcnt[i] = 0;
    if (i < B_ * 2 * D_) g_qstar[i] = 0.f;
    if (i < B_ * D_) { g_hl[i] = 0.f; g_cl[i] = 0.f; }
}

// ---------------- convert + counts (detect inline) (launch #2) ----------------
__global__ void convert_counts_kernel(const void* ei, const void* ba) {
    int i = blockIdx.x * blockDim.x + threadIdx.x;
    // inline dtype detection (cheap, cached)
    int f0 = 1, f1 = 1;
    {
        const long long* p = (const long long*)ei;
#pragma unroll
        for (int t = 0; t < 8; t++) { long long v = p[t]; if (v < 0 || v >= N_) f0 = 0; }
#pragma unroll
        for (int t = 0; t < 8; t++) { long long v = p[2 * E_ / 2 - 8 + t]; if (v < 0 || v >= N_) f0 = 0; }
    }
    {
        const long long* p = (const long long*)ba;
#pragma unroll
        for (int t = 0; t < 8; t++) { long long v = p[t]; if (v < 0 || v >= B_) f1 = 0; }
#pragma unroll
        for (int t = 0; t < 8; t++) { long long v = p[N_ / 2 - 8 + t]; if (v < 0 || v >= B_) f1 = 0; }
    }
    if (i < E_) {
        int s, d;
        if (f0) {
            const long long* p = (const long long*)ei;
            s = (int)p[i]; d = (int)p[E_ + i];
        } else {
            const int* p = (const int*)ei;
            s = p[i]; d = p[E_ + i];
        }
        g_src[i] = s;
        g_dst[i] = d;
        atomicAdd(&g_cnt[d], 1.0f);
    }
    if (i < N_) {
        int b;
        if (f1) {
            const long long* p = (const long long*)ba;
            b = (int)p[i];
        } else {
            const int* p = (const int*)ba;
            b = p[i];
        }
        g_batch[i] = b;
        atomicAdd(&g_gcnt[b], 1);
    }
}

// ---------------- prefix (launch #3) ----------------
__global__ void scan_ptr_kernel() {
    if (threadIdx.x != 0) return;
    int acc = 0;
    g_ptr[0] = 0;
    for (int b = 0; b < B_; b++) { acc += g_gcnt[b]; g_ptr[b + 1] = acc; }
}

// ============ fused NNConv message GEMM: msg = (r ⊗ h) @ W3, no ew tensor ============
// C[e,f] = sum_{k,d} r[e,k]*h[e,d] * W2[d*64+f,k]  (+ bias via virtual k=64, r=1)
// CTA: 128 edges, 256 threads (8 warps: 4 m-tiles x 2 n-tiles of 32x32).
// K = 65 chunks of 64; A-chunk built in smem as rk * h-row (fp16), B-chunk 8KB L2-resident.
#define EWP 72      // half-unit row stride (144B): conflict-free ldmatrix
#define HS_OFF 0
#define AZ_OFF (128 * EWP)                  // 9216
#define RS_OFF (2 * 128 * EWP)              // 18432 (width 68)
#define BS_OFF (RS_OFF + 128 * 68)          // 27136
#define MSG_SMEM ((BS_OFF + 64 * EWP) * 2)  // 63488 bytes

__device__ __forceinline__ void ldsm4(uint32_t addr, uint32_t* r) {
    asm volatile("ldmatrix.sync.aligned.m8n8.x4.shared.b16 {%0,%1,%2,%3}, [%4];"
                 : "=r"(r[0]), "=r"(r[1]), "=r"(r[2]), "=r"(r[3]) : "r"(addr));
}
__device__ __forceinline__ void mma_fp16(float* c, const uint32_t* a, uint32_t b0, uint32_t b1) {
    asm volatile(
        "mma.sync.aligned.m16n8k16.row.col.f32.f16.f16.f32 "
        "{%0,%1,%2,%3}, {%4,%5,%6,%7}, {%8,%9}, {%0,%1,%2,%3};"
        : "+f"(c[0]), "+f"(c[1]), "+f"(c[2]), "+f"(c[3])
        : "r"(a[0]), "r"(a[1]), "r"(a[2]), "r"(a[3]), "r"(b0), "r"(b1));
}

__global__ void __launch_bounds__(256) msg_gemm_kernel(int it) {
    extern __shared__ __half sm[];
    uint32_t sb = smem_u32(sm);
    int tid = threadIdx.x;
    int e0 = blockIdx.x * 128;

    // stage HS (gathered src h, fp32->fp16) and RS (r fp16, +1.0 at k=64)
    for (int i = tid; i < 128 * 32; i += 256) {
        int row = i >> 5, c2 = i & 31;
        int e = e0 + row;
        float2 hv = (e < E_) ? ((const float2*)&g_h[g_src[e] * 64])[c2] : make_float2(0.f, 0.f);
        *(__half2*)&sm[HS_OFF + row * EWP + c2 * 2] = __floats2half2_rn(hv.x, hv.y);
    }
    for (int i = tid; i < 128 * 32; i += 256) {
        int row = i >> 5, c2 = i & 31;
        int e = e0 + row;
        __half2 rv = (e < E_) ? *(const __half2*)&g_rh[e * 64 + c2 * 2]
                              : __half2half2(__float2half(0.f));
        *(__half2*)&sm[RS_OFF + row * 68 + c2 * 2] = rv;
    }
    if (tid < 128) sm[RS_OFF + tid * 68 + 64] = __float2half(1.0f);  // virtual bias-k
    __syncthreads();

    int w = tid >> 5, lane = tid & 31;
    int wm = w & 3, wn = w >> 2;      // warp: rows wm*32, cols wn*32
    int r8 = lane & 7, q = lane >> 3;
    int a_row = ((q & 1) ? 8 : 0) + r8;
    int a_col = (q >= 2) ? 8 : 0;
    int b_row = ((q >= 2) ? 8 : 0) + r8;
    int b_col = (q & 1) ? 8 : 0;
    int g = lane >> 2, qq = lane & 3;

    float c[2][4][4];
#pragma unroll
    for (int t = 0; t < 2; t++)
#pragma unroll
        for (int n = 0; n < 4; n++)
#pragma unroll
            for (int j = 0; j < 4; j++) c[t][n][j] = 0.f;

    for (int kc = 0; kc < 65; kc++) {
        // stage AZ = RS[:,kc] (*) HS   (broadcast scalar per row)
        for (int i = tid; i < 128 * 32; i += 256) {
            int row = i >> 5, c2 = i & 31;
            __half2 rk2 = __half2half2(sm[RS_OFF + row * 68 + kc]);
            __half2 hv = *(const __half2*)&sm[HS_OFF + row * EWP + c2 * 2];
            *(__half2*)&sm[AZ_OFF + row * EWP + c2 * 2] = __hmul2(rk2, hv);
        }
        // stage BS chunk (64x64 halfs = 8KB) via cp.async
        for (int i = tid; i < 512; i += 256) {
            int f = i >> 3, d8 = i & 7;
            cp16(sb + (uint32_t)(BS_OFF + f * EWP + d8 * 8) * 2,
                 &g_w3[kc * DD_ + f * 64 + d8 * 8]);
        }
        asm volatile("cp.async.commit_group;" ::: "memory");
        asm volatile("cp.async.wait_group 0;" ::: "memory");
        __syncthreads();

#pragma unroll
        for (int k0 = 0; k0 < 4; k0++) {
            uint32_t a[2][4], b[2][4];
#pragma unroll
            for (int t = 0; t < 2; t++) {
                uint32_t ad = sb + (uint32_t)(AZ_OFF +
                    (wm * 32 + t * 16 + a_row) * EWP + k0 * 16 + a_col) * 2;
                ldsm4(ad, a[t]);
            }
#pragma unroll
            for (int p = 0; p < 2; p++) {
                uint32_t bd = sb + (uint32_t)(BS_OFF +
                    (wn * 32 + p * 16 + b_row) * EWP + k0 * 16 + b_col) * 2;
                ldsm4(bd, b[p]);
            }
#pragma unroll
            for (int t = 0; t < 2; t++)
#pragma unroll
                for (int n = 0; n < 4; n++) {
                    int p = n >> 1, s = (n & 1) * 2;
                    mma_fp16(c[t][n], a[t], b[p][s], b[p][s + 1]);
                }
        }
        __syncthreads();
    }

    // scatter to agg[dst]
    float* agg = &g_agg[(size_t)it * N_ * D_];
#pragma unroll
    for (int t = 0; t < 2; t++) {
        int ge0 = e0 + wm * 32 + t * 16 + g;
        int ge1 = ge0 + 8;
        int dst0 = (ge0 < E_) ? g_dst[ge0] : -1;
        int dst1 = (ge1 < E_) ? g_dst[ge1] : -1;
#pragma unroll
        for (int n = 0; n < 4; n++) {
            int col = wn * 32 + n * 8 + qq * 2;
            if (dst0 >= 0) {
                atomicAdd(&agg[dst0 * 64 + col], c[t][n][0]);
                atomicAdd(&agg[dst0 * 64 + col + 1], c[t][n][1]);
            }
            if (dst1 >= 0) {
                atomicAdd(&agg[dst1 * 64 + col], c[t][n][2]);
                atomicAdd(&agg[dst1 * 64 + col + 1], c[t][n][3]);
            }
        }
    }
}

// ---------------- GRU update over node tiles of 16 ----------------
__global__ void __launch_bounds__(192) gru_kernel(const float* __restrict__ Wih,
                                                  const float* __restrict__ bih,
                                                  const float* __restrict__ Whh,
                                                  const float* __restrict__ bhh,
                                                  const float* __restrict__ bconv,
                                                  int it) {
    __shared__ float Msm[16][64];
    __shared__ float Hsm[16][64];
    __shared__ float GI[16][192];
    __shared__ float GH[16][192];
    int n0 = blockIdx.x * 16;
    int tid = threadIdx.x;
    const float* agg = &g_agg[(size_t)it * N_ * D_];

    for (int idx = tid; idx < 16 * 64; idx += 192) {
        int m = idx >> 6, k = idx & 63;
        int n = n0 + m;
        if (n < N_) {
            float cdeg = fmaxf(g_cnt[n], 1.0f);
            Msm[m][k] = fmaxf(agg[n * 64 + k] / cdeg + bconv[k], 0.f);
            Hsm[m][k] = g_h[n * 64 + k];
        } else {
            Msm[m][k] = 0.f;
            Hsm[m][k] = 0.f;
        }
    }
    __syncthreads();

    float wih[64], whh[64];
    const float* wi = Wih + tid * 64;
    const float* wh = Whh + tid * 64;
#pragma unroll
    for (int k = 0; k < 64; k++) { wih[k] = __ldg(&wi[k]); whh[k] = __ldg(&wh[k]); }
    float bi = bih[tid], bh = bhh[tid];

#pragma unroll 4
    for (int m = 0; m < 16; m++) {
        float ai = bi, ah = bh;
#pragma unroll
        for (int k = 0; k < 64; k++) {
            ai += Msm[m][k] * wih[k];
            ah += Hsm[m][k] * whh[k];
        }
        GI[m][tid] = ai;
        GH[m][tid] = ah;
    }
    __syncthreads();

    for (int idx = tid; idx < 16 * 64; idx += 192) {
        int m = idx >> 6, f = idx & 63;
        int n = n0 + m;
        if (n >= N_) continue;
        float r = sigm(GI[m][f] + GH[m][f]);
        float z = sigm(GI[m][64 + f] + GH[m][64 + f]);
        float nn = tanhf(GI[m][128 + f] + r * GH[m][128 + f]);
        float hnew = (1.f - z) * nn + z * Hsm[m][f];
        g_h[n * 64 + f] = hnew;
    }
}

// ---------------- Set2Set LSTM cell (8 graphs per 256-thread block) ----------------
__global__ void lstm_kernel(const float* __restrict__ Wih, const float* __restrict__ bih,
                            const float* __restrict__ Whh, const float* __restrict__ bhh) {
    __shared__ float qs[8][128];
    __shared__ float hs[8][64];
    __shared__ float gsm[8][256];
    int b0 = blockIdx.x * 8;
    int tid = threadIdx.x;

    for (int idx = tid; idx < 8 * 128; idx += 256) {
        int g = idx >> 7, k = idx & 127;
        int b = b0 + g;
        qs[g][k] = (b < B_) ? g_qstar[b * 128 + k] : 0.f;
    }
    for (int idx = tid; idx < 8 * 64; idx += 256) {
        int g = idx >> 6, k = idx & 63;
        int b = b0 + g;
        hs[g][k] = (b < B_) ? g_hl[b * 64 + k] : 0.f;
    }
    __syncthreads();

    int j = tid;
    float acc[8];
    float bsum = bih[j] + bhh[j];
#pragma unroll
    for (int g = 0; g < 8; g++) acc[g] = bsum;
    const float* wi = Wih + j * 128;
    const float* wh = Whh + j * 64;
#pragma unroll 4
    for (int k = 0; k < 128; k++) {
        float w = __ldg(&wi[k]);
#pragma unroll
        for (int g = 0; g < 8; g++) acc[g] += qs[g][k] * w;
    }
#pragma unroll 4
    for (int k = 0; k < 64; k++) {
        float w = __ldg(&wh[k]);
#pragma unroll
        for (int g = 0; g < 8; g++) acc[g] += hs[g][k] * w;
    }
#pragma unroll
    for (int g = 0; g < 8; g++) gsm[g][j] = acc[g];
    __syncthreads();

    for (int idx = tid; idx < 8 * 64; idx += 256) {
        int g = idx >> 6, f = idx & 63;
        int b = b0 + g;
        if (b >= B_) continue;
        float ig = sigm(gsm[g][f]);
        float fg = sigm(gsm[g][64 + f]);
        float gg = tanhf(gsm[g][128 + f]);
        float og = sigm(gsm[g][192 + f]);
        float c = fg * g_cl[b * 64 + f] + ig * gg;
        float h = og * tanhf(c);
        g_cl[b * 64 + f] = c;
        g_hl[b * 64 + f] = h;
    }
}

// ---------------- attention (segment softmax + weighted sum) per graph ----------------
__global__ void attn_kernel() {
    int b = blockIdx.x;
    int tid = threadIdx.x;   // 128 threads
    __shared__ float qv[64];
    __shared__ float red[128];
    if (tid < 64) qv[tid] = g_hl[b * 64 + tid];
    __syncthreads();

    int s = g_ptr[b], eend = g_ptr[b + 1];

    float lmax = -INFINITY;
    for (int n = s + tid; n < eend; n += 128) {
        const float4* hr = (const float4*)&g_h[n * 64];
        const float4* qq = (const float4*)qv;
        float d = 0.f;
#pragma unroll
        for (int k = 0; k < 16; k++) {
            float4 a = hr[k], c = qq[k];
            d += a.x * c.x + a.y * c.y + a.z * c.z + a.w * c.w;
        }
        g_e[n] = d;
        lmax = fmaxf(lmax, d);
    }
    red[tid] = lmax;
    __syncthreads();
    for (int o = 64; o > 0; o >>= 1) {
        if (tid < o) red[tid] = fmaxf(red[tid], red[tid + o]);
        __syncthreads();
    }
    float mmax = red[0];
    __syncthreads();

    float lsum = 0.f;
    for (int n = s + tid; n < eend; n += 128) {
        float a = expf(g_e[n] - mmax);
        g_e[n] = a;
        lsum += a;
    }
    red[tid] = lsum;
    __syncthreads();
    for (int o = 64; o > 0; o >>= 1) {
        if (tid < o) red[tid] += red[tid + o];
        __syncthreads();
    }
    float den = red[0];
    __syncthreads();

    if (tid < 64) {
        float accr = 0.f;
        for (int n = s; n < eend; n++) accr += g_e[n] * g_h[n * 64 + tid];
        float rv = (den > 0.f) ? accr / den : 0.f;
        g_qstar[b * 128 + tid] = qv[tid];
        g_qstar[b * 128 + 64 + tid] = rv;
    }
}

// ---------------- output head ----------------
__global__ void out_head_kernel(const float* __restrict__ Wo1, const float* __restrict__ bo1,
                                const float* __restrict__ Wo2, const float* __restrict__ bo2,
                                float* __restrict__ out) {
    int b = blockIdx.x;
    int j = threadIdx.x;   // 64
    __shared__ float qs[128];
    __shared__ float hr[64];
    qs[j] = g_qstar[b * 128 + j];
    qs[64 + j] = g_qstar[b * 128 + 64 + j];
    __syncthreads();
    float acc = bo1[j];
    const float* wr = Wo1 + j * 128;
#pragma unroll 4
    for (int k = 0; k < 128; k++) acc += qs[k] * wr[k];
    acc = fmaxf(acc, 0.f) * Wo2[j];
    hr[j] = acc;
    __syncthreads();
    for (int o = 32; o > 0; o >>= 1) {
        if (j < o) hr[j] += hr[j + o];
        __syncthreads();
    }
    if (j == 0) out[b] = hr[0] + bo2[0];
}

// ---------------- host launch ----------------
extern "C" void kernel_launch(void* const* d_in, const int* in_sizes, int n_in,
                              void* d_out, int out_size) {
    const float* x      = (const float*)d_in[0];
    const float* eattr  = (const float*)d_in[1];
    const float* W_in   = (const float*)d_in[2];
    const float* b_in   = (const float*)d_in[3];
    const float* W_e1   = (const float*)d_in[4];
    const float* b_e1   = (const float*)d_in[5];
    const float* W_e2   = (const float*)d_in[6];
    const float* b_e2   = (const float*)d_in[7];
    const float* b_conv = (const float*)d_in[8];
    const float* W_ih   = (const float*)d_in[9];
    const float* b_ih   = (const float*)d_in[10];
    const float* W_hh   = (const float*)d_in[11];
    const float* b_hh   = (const float*)d_in[12];
    const float* W_ih_l = (const float*)d_in[13];
    const float* b_ih_l = (const float*)d_in[14];
    const float* W_hh_l = (const float*)d_in[15];
    const float* b_hh_l = (const float*)d_in[16];
    const float* W_o1   = (const float*)d_in[17];
    const float* b_o1   = (const float*)d_in[18];
    const float* W_o2   = (const float*)d_in[19];
    const float* b_o2   = (const float*)d_in[20];
    const void*  eidx   = d_in[21];
    const void*  batch  = d_in[22];
    float* out = (float*)d_out;

    static bool attr_set = false;
    if (!attr_set) {
        cudaFuncSetAttribute(msg_gemm_kernel,
                             cudaFuncAttributeMaxDynamicSharedMemorySize, MSG_SMEM);
        attr_set = true;
    }

    int nblk = (E_ + 127) / 128;  // 157

    prep_kernel<<<(3 * N_ * D_ + 255) / 256, 256>>>(x, W_in, b_in, eattr, W_e1, b_e1,
                                                    W_e2, b_e2);             // 1
    convert_counts_kernel<<<(E_ + 255) / 256, 256>>>(eidx, batch);           // 2
    scan_ptr_kernel<<<1, 32>>>();                                            // 3

    // 3 message-passing + GRU iterations (no ew tensor; Z@W3 GEMM per iter)
    msg_gemm_kernel<<<nblk, 256, MSG_SMEM>>>(0);                             // 4 (profiled)
    gru_kernel<<<(N_ + 15) / 16, 192>>>(W_ih, b_ih, W_hh, b_hh, b_conv, 0);  // 5
    msg_gemm_kernel<<<nblk, 256, MSG_SMEM>>>(1);                             // 6
    gru_kernel<<<(N_ + 15) / 16, 192>>>(W_ih, b_ih, W_hh, b_hh, b_conv, 1);  // 7
    msg_gemm_kernel<<<nblk, 256, MSG_SMEM>>>(2);                             // 8
    gru_kernel<<<(N_ + 15) / 16, 192>>>(W_ih, b_ih, W_hh, b_hh, b_conv, 2);  // 9

    // Set2Set (q_star/hl/cl pre-zeroed)
    for (int it = 0; it < 3; it++) {
        lstm_kernel<<<(B_ + 7) / 8, 256>>>(W_ih_l, b_ih_l, W_hh_l, b_hh_l);
        attn_kernel<<<B_, 128>>>();
    }

    out_head_kernel<<<B_, 64>>>(W_o1, b_o1, W_o2, b_o2, out);
}

// round 14
// speedup vs baseline: 1.0813x; 1.0813x over previous
#include <cuda_runtime.h>
#include <cuda_fp16.h>
#include <math.h>
#include <stdint.h>

#define N_  10000
#define E_  20000
#define B_  400
#define ND_ 32
#define ED_ 16
#define D_  64
#define DD_ 4096   // D*D
#define KSPLIT 5   // K-chunks split across blockIdx.y (65 = 5*13)
#define KCPER 13

// ---------------- scratch (device globals; no cudaMalloc allowed) ----------------
__device__ float g_h[N_ * D_];            // node hidden / out (fp32)
__device__ __half g_rh[E_ * D_];          // edge MLP hidden, fp16
__device__ __half g_w3[65 * DD_];         // permuted W_e2 [k][f][d] (+ chunk 64 = b2^T)
__device__ float g_agg[3 * N_ * D_];      // scatter accumulators (one per iteration)
__device__ float g_cnt[N_];               // dst degree
__device__ int   g_src[E_], g_dst[E_], g_batch[N_];
__device__ int   g_gcnt[B_];
__device__ int   g_ptr[B_ + 1];
__device__ float g_qstar[B_ * 2 * D_];
__device__ float g_hl[B_ * D_];
__device__ float g_cl[B_ * D_];
__device__ float g_e[N_];                 // per-node attention logits / weights

__device__ __forceinline__ float sigm(float x) { return 1.f / (1.f + expf(-x)); }

__device__ __forceinline__ uint32_t smem_u32(const void* p) {
    uint32_t a;
    asm("{ .reg .u64 t; cvta.to.shared.u64 t, %1; cvt.u32.u64 %0, t; }" : "=r"(a) : "l"(p));
    return a;
}
__device__ __forceinline__ void cp16(uint32_t dst, const void* src) {
    asm volatile("cp.async.cg.shared.global [%0], [%1], 16;" :: "r"(dst), "l"(src));
}

// ---------------- prep: encoders + W3 build + zero init (launch #1) ----------------
__global__ void prep_kernel(const float* __restrict__ x,
                            const float* __restrict__ W_in, const float* __restrict__ b_in,
                            const float* __restrict__ ea,
                            const float* __restrict__ W_e1, const float* __restrict__ b_e1,
                            const float* __restrict__ W_e2, const float* __restrict__ b_e2) {
    int i = blockIdx.x * blockDim.x + threadIdx.x;
    if (i < N_ * D_) {
        int n = i >> 6, f = i & 63;
        float acc = b_in[f];
        const float* xr = x + n * ND_;
        const float* wr = W_in + f * ND_;
#pragma unroll
        for (int k = 0; k < ND_; k++) acc += xr[k] * wr[k];
        g_h[i] = fmaxf(acc, 0.f);
    } else if (i < N_ * D_ + E_ * D_) {
        int j = i - N_ * D_;
        int e = j >> 6, f = j & 63;
        float acc = b_e1[f];
        const float* er = ea + e * ED_;
        const float* wr = W_e1 + f * ED_;
#pragma unroll
        for (int k = 0; k < ED_; k++) acc += er[k] * wr[k];
        g_rh[j] = __float2half(fmaxf(acc, 0.f));
    }
    if (i < 65 * DD_) {
        int k = i >> 12, rem = i & 4095;
        int f = rem >> 6, d = rem & 63;
        float v = (k < 64) ? W_e2[(d * 64 + f) * 64 + k] : b_e2[d * 64 + f];
        g_w3[i] = __float2half(v);
    }
    if (i < 3 * N_ * D_) g_agg[i] = 0.f;
    if (i < N_) g_cnt[i] = 0.f;
    if (i < B_) g_gcnt[i] = 0;
    if (i < B_ * 2 * D_) g_qstar[i] = 0.f;
    if (i < B_ * D_) { g_hl[i] = 0.f; g_cl[i] = 0.f; }
}

// ---------------- convert + counts (detect inline) (launch #2) ----------------
__global__ void convert_counts_kernel(const void* ei, const void* ba) {
    int i = blockIdx.x * blockDim.x + threadIdx.x;
    int f0 = 1, f1 = 1;
    {
        const long long* p = (const long long*)ei;
#pragma unroll
        for (int t = 0; t < 8; t++) { long long v = p[t]; if (v < 0 || v >= N_) f0 = 0; }
#pragma unroll
        for (int t = 0; t < 8; t++) { long long v = p[2 * E_ / 2 - 8 + t]; if (v < 0 || v >= N_) f0 = 0; }
    }
    {
        const long long* p = (const long long*)ba;
#pragma unroll
        for (int t = 0; t < 8; t++) { long long v = p[t]; if (v < 0 || v >= B_) f1 = 0; }
#pragma unroll
        for (int t = 0; t < 8; t++) { long long v = p[N_ / 2 - 8 + t]; if (v < 0 || v >= B_) f1 = 0; }
    }
    if (i < E_) {
        int s, d;
        if (f0) {
            const long long* p = (const long long*)ei;
            s = (int)p[i]; d = (int)p[E_ + i];
        } else {
            const int* p = (const int*)ei;
            s = p[i]; d = p[E_ + i];
        }
        g_src[i] = s;
        g_dst[i] = d;
        atomicAdd(&g_cnt[d], 1.0f);
    }
    if (i < N_) {
        int b;
        if (f1) {
            const long long* p = (const long long*)ba;
            b = (int)p[i];
        } else {
            const int* p = (const int*)ba;
            b = p[i];
        }
        g_batch[i] = b;
        atomicAdd(&g_gcnt[b], 1);
    }
}

// ---------------- prefix (launch #3) ----------------
__global__ void scan_ptr_kernel() {
    if (threadIdx.x != 0) return;
    int acc = 0;
    g_ptr[0] = 0;
    for (int b = 0; b < B_; b++) { acc += g_gcnt[b]; g_ptr[b + 1] = acc; }
}

// ============ fused NNConv message GEMM, K-split: msg = (r ⊗ h) @ W3 ============
// C[e,f] = sum_{k,d} r[e,k]*h[e,d]*W2[d*64+f,k] (+bias via virtual k=64).
// blockIdx.x: 128-edge tile; blockIdx.y: 13-chunk K range. Partial sums atomically
// accumulated into g_agg (zero-initialized) — K-split is free parallelism.
#define EWP 72
#define HS_OFF 0
#define AZ_OFF (128 * EWP)                  // 9216
#define RS_OFF (2 * 128 * EWP)              // 18432 (width 68)
#define BS_OFF (RS_OFF + 128 * 68)          // 27136
#define MSG_SMEM ((BS_OFF + 64 * EWP) * 2)  // 63488 bytes

__device__ __forceinline__ void ldsm4(uint32_t addr, uint32_t* r) {
    asm volatile("ldmatrix.sync.aligned.m8n8.x4.shared.b16 {%0,%1,%2,%3}, [%4];"
                 : "=r"(r[0]), "=r"(r[1]), "=r"(r[2]), "=r"(r[3]) : "r"(addr));
}
__device__ __forceinline__ void mma_fp16(float* c, const uint32_t* a, uint32_t b0, uint32_t b1) {
    asm volatile(
        "mma.sync.aligned.m16n8k16.row.col.f32.f16.f16.f32 "
        "{%0,%1,%2,%3}, {%4,%5,%6,%7}, {%8,%9}, {%0,%1,%2,%3};"
        : "+f"(c[0]), "+f"(c[1]), "+f"(c[2]), "+f"(c[3])
        : "r"(a[0]), "r"(a[1]), "r"(a[2]), "r"(a[3]), "r"(b0), "r"(b1));
}

__global__ void __launch_bounds__(256) msg_gemm_kernel(int it) {
    extern __shared__ __half sm[];
    uint32_t sb = smem_u32(sm);
    int tid = threadIdx.x;
    int e0 = blockIdx.x * 128;
    int kc0 = blockIdx.y * KCPER;

    // stage HS (gathered src h, fp32->fp16) and RS (r fp16, +1.0 at k=64)
    for (int i = tid; i < 128 * 32; i += 256) {
        int row = i >> 5, c2 = i & 31;
        int e = e0 + row;
        float2 hv = (e < E_) ? ((const float2*)&g_h[g_src[e] * 64])[c2] : make_float2(0.f, 0.f);
        *(__half2*)&sm[HS_OFF + row * EWP + c2 * 2] = __floats2half2_rn(hv.x, hv.y);
    }
    for (int i = tid; i < 128 * 32; i += 256) {
        int row = i >> 5, c2 = i & 31;
        int e = e0 + row;
        __half2 rv = (e < E_) ? *(const __half2*)&g_rh[e * 64 + c2 * 2]
                              : __half2half2(__float2half(0.f));
        *(__half2*)&sm[RS_OFF + row * 68 + c2 * 2] = rv;
    }
    if (tid < 128) sm[RS_OFF + tid * 68 + 64] = __float2half(1.0f);
    __syncthreads();

    int w = tid >> 5, lane = tid & 31;
    int wm = w & 3, wn = w >> 2;
    int r8 = lane & 7, q = lane >> 3;
    int a_row = ((q & 1) ? 8 : 0) + r8;
    int a_col = (q >= 2) ? 8 : 0;
    int b_row = ((q >= 2) ? 8 : 0) + r8;
    int b_col = (q & 1) ? 8 : 0;
    int g = lane >> 2, qq = lane & 3;

    float c[2][4][4];
#pragma unroll
    for (int t = 0; t < 2; t++)
#pragma unroll
        for (int n = 0; n < 4; n++)
#pragma unroll
            for (int j = 0; j < 4; j++) c[t][n][j] = 0.f;

#pragma unroll 1
    for (int kk = 0; kk < KCPER; kk++) {
        int kc = kc0 + kk;
        // AZ = RS[:,kc] (*) HS
        for (int i = tid; i < 128 * 32; i += 256) {
            int row = i >> 5, c2 = i & 31;
            __half2 rk2 = __half2half2(sm[RS_OFF + row * 68 + kc]);
            __half2 hv = *(const __half2*)&sm[HS_OFF + row * EWP + c2 * 2];
            *(__half2*)&sm[AZ_OFF + row * EWP + c2 * 2] = __hmul2(rk2, hv);
        }
        // BS chunk (8KB) via cp.async
        for (int i = tid; i < 512; i += 256) {
            int f = i >> 3, d8 = i & 7;
            cp16(sb + (uint32_t)(BS_OFF + f * EWP + d8 * 8) * 2,
                 &g_w3[kc * DD_ + f * 64 + d8 * 8]);
        }
        asm volatile("cp.async.commit_group;" ::: "memory");
        asm volatile("cp.async.wait_group 0;" ::: "memory");
        __syncthreads();

#pragma unroll
        for (int k0 = 0; k0 < 4; k0++) {
            uint32_t a[2][4], b[2][4];
#pragma unroll
            for (int t = 0; t < 2; t++) {
                uint32_t ad = sb + (uint32_t)(AZ_OFF +
                    (wm * 32 + t * 16 + a_row) * EWP + k0 * 16 + a_col) * 2;
                ldsm4(ad, a[t]);
            }
#pragma unroll
            for (int p = 0; p < 2; p++) {
                uint32_t bd = sb + (uint32_t)(BS_OFF +
                    (wn * 32 + p * 16 + b_row) * EWP + k0 * 16 + b_col) * 2;
                ldsm4(bd, b[p]);
            }
#pragma unroll
            for (int t = 0; t < 2; t++)
#pragma unroll
                for (int n = 0; n < 4; n++) {
                    int p = n >> 1, s = (n & 1) * 2;
                    mma_fp16(c[t][n], a[t], b[p][s], b[p][s + 1]);
                }
        }
        __syncthreads();
    }

    // scatter partial sums to agg[dst]
    float* agg = &g_agg[(size_t)it * N_ * D_];
#pragma unroll
    for (int t = 0; t < 2; t++) {
        int ge0 = e0 + wm * 32 + t * 16 + g;
        int ge1 = ge0 + 8;
        int dst0 = (ge0 < E_) ? g_dst[ge0] : -1;
        int dst1 = (ge1 < E_) ? g_dst[ge1] : -1;
#pragma unroll
        for (int n = 0; n < 4; n++) {
            int col = wn * 32 + n * 8 + qq * 2;
            if (dst0 >= 0) {
                atomicAdd(&agg[dst0 * 64 + col], c[t][n][0]);
                atomicAdd(&agg[dst0 * 64 + col + 1], c[t][n][1]);
            }
            if (dst1 >= 0) {
                atomicAdd(&agg[dst1 * 64 + col], c[t][n][2]);
                atomicAdd(&agg[dst1 * 64 + col + 1], c[t][n][3]);
            }
        }
    }
}

// ---------------- GRU update over node tiles of 16 ----------------
__global__ void __launch_bounds__(192) gru_kernel(const float* __restrict__ Wih,
                                                  const float* __restrict__ bih,
                                                  const float* __restrict__ Whh,
                                                  const float* __restrict__ bhh,
                                                  const float* __restrict__ bconv,
                                                  int it) {
    __shared__ float Msm[16][64];
    __shared__ float Hsm[16][64];
    __shared__ float GI[16][192];
    __shared__ float GH[16][192];
    int n0 = blockIdx.x * 16;
    int tid = threadIdx.x;
    const float* agg = &g_agg[(size_t)it * N_ * D_];

    for (int idx = tid; idx < 16 * 64; idx += 192) {
        int m = idx >> 6, k = idx & 63;
        int n = n0 + m;
        if (n < N_) {
            float cdeg = fmaxf(g_cnt[n], 1.0f);
            Msm[m][k] = fmaxf(agg[n * 64 + k] / cdeg + bconv[k], 0.f);
            Hsm[m][k] = g_h[n * 64 + k];
        } else {
            Msm[m][k] = 0.f;
            Hsm[m][k] = 0.f;
        }
    }
    __syncthreads();

    float wih[64], whh[64];
    const float* wi = Wih + tid * 64;
    const float* wh = Whh + tid * 64;
#pragma unroll
    for (int k = 0; k < 64; k++) { wih[k] = __ldg(&wi[k]); whh[k] = __ldg(&wh[k]); }
    float bi = bih[tid], bh = bhh[tid];

#pragma unroll 4
    for (int m = 0; m < 16; m++) {
        float ai = bi, ah = bh;
#pragma unroll
        for (int k = 0; k < 64; k++) {
            ai += Msm[m][k] * wih[k];
            ah += Hsm[m][k] * whh[k];
        }
        GI[m][tid] = ai;
        GH[m][tid] = ah;
    }
    __syncthreads();

    for (int idx = tid; idx < 16 * 64; idx += 192) {
        int m = idx >> 6, f = idx & 63;
        int n = n0 + m;
        if (n >= N_) continue;
        float r = sigm(GI[m][f] + GH[m][f]);
        float z = sigm(GI[m][64 + f] + GH[m][64 + f]);
        float nn = tanhf(GI[m][128 + f] + r * GH[m][128 + f]);
        float hnew = (1.f - z) * nn + z * Hsm[m][f];
        g_h[n * 64 + f] = hnew;
    }
}

// ---------------- Set2Set LSTM cell (8 graphs per 256-thread block) ----------------
__global__ void lstm_kernel(const float* __restrict__ Wih, const float* __restrict__ bih,
                            const float* __restrict__ Whh, const float* __restrict__ bhh) {
    __shared__ float qs[8][128];
    __shared__ float hs[8][64];
    __shared__ float gsm[8][256];
    int b0 = blockIdx.x * 8;
    int tid = threadIdx.x;

    for (int idx = tid; idx < 8 * 128; idx += 256) {
        int g = idx >> 7, k = idx & 127;
        int b = b0 + g;
        qs[g][k] = (b < B_) ? g_qstar[b * 128 + k] : 0.f;
    }
    for (int idx = tid; idx < 8 * 64; idx += 256) {
        int g = idx >> 6, k = idx & 63;
        int b = b0 + g;
        hs[g][k] = (b < B_) ? g_hl[b * 64 + k] : 0.f;
    }
    __syncthreads();

    int j = tid;
    float acc[8];
    float bsum = bih[j] + bhh[j];
#pragma unroll
    for (int g = 0; g < 8; g++) acc[g] = bsum;
    const float* wi = Wih + j * 128;
    const float* wh = Whh + j * 64;
#pragma unroll 4
    for (int k = 0; k < 128; k++) {
        float w = __ldg(&wi[k]);
#pragma unroll
        for (int g = 0; g < 8; g++) acc[g] += qs[g][k] * w;
    }
#pragma unroll 4
    for (int k = 0; k < 64; k++) {
        float w = __ldg(&wh[k]);
#pragma unroll
        for (int g = 0; g < 8; g++) acc[g] += hs[g][k] * w;
    }
#pragma unroll
    for (int g = 0; g < 8; g++) gsm[g][j] = acc[g];
    __syncthreads();

    for (int idx = tid; idx < 8 * 64; idx += 256) {
        int g = idx >> 6, f = idx & 63;
        int b = b0 + g;
        if (b >= B_) continue;
        float ig = sigm(gsm[g][f]);
        float fg = sigm(gsm[g][64 + f]);
        float gg = tanhf(gsm[g][128 + f]);
        float og = sigm(gsm[g][192 + f]);
        float c = fg * g_cl[b * 64 + f] + ig * gg;
        float h = og * tanhf(c);
        g_cl[b * 64 + f] = c;
        g_hl[b * 64 + f] = h;
    }
}

// ---------------- attention (segment softmax + weighted sum) per graph ----------------
__global__ void attn_kernel() {
    int b = blockIdx.x;
    int tid = threadIdx.x;   // 128 threads
    __shared__ float qv[64];
    __shared__ float red[128];
    __shared__ float racc[2][64];
    if (tid < 64) qv[tid] = g_hl[b * 64 + tid];
    __syncthreads();

    int s = g_ptr[b], eend = g_ptr[b + 1];

    float lmax = -INFINITY;
    for (int n = s + tid; n < eend; n += 128) {
        const float4* hr = (const float4*)&g_h[n * 64];
        const float4* qq = (const float4*)qv;
        float d = 0.f;
#pragma unroll
        for (int k = 0; k < 16; k++) {
            float4 a = hr[k], c = qq[k];
            d += a.x * c.x + a.y * c.y + a.z * c.z + a.w * c.w;
        }
        g_e[n] = d;
        lmax = fmaxf(lmax, d);
    }
    red[tid] = lmax;
    __syncthreads();
    for (int o = 64; o > 0; o >>= 1) {
        if (tid < o) red[tid] = fmaxf(red[tid], red[tid + o]);
        __syncthreads();
    }
    float mmax = red[0];
    __syncthreads();

    float lsum = 0.f;
    for (int n = s + tid; n < eend; n += 128) {
        float a = expf(g_e[n] - mmax);
        g_e[n] = a;
        lsum += a;
    }
    red[tid] = lsum;
    __syncthreads();
    for (int o = 64; o > 0; o >>= 1) {
        if (tid < o) red[tid] += red[tid + o];
        __syncthreads();
    }
    float den = red[0];
    __syncthreads();

    // weighted sum, 2-way node-parity parallel
    {
        int par = tid >> 6;      // 0/1
        int col = tid & 63;
        float accr = 0.f;
        for (int n = s + par; n < eend; n += 2) accr += g_e[n] * g_h[n * 64 + col];
        racc[par][col] = accr;
    }
    __syncthreads();
    if (tid < 64) {
        float rv = racc[0][tid] + racc[1][tid];
        rv = (den > 0.f) ? rv / den : 0.f;
        g_qstar[b * 128 + tid] = qv[tid];
        g_qstar[b * 128 + 64 + tid] = rv;
    }
}

// ---------------- output head ----------------
__global__ void out_head_kernel(const float* __restrict__ Wo1, const float* __restrict__ bo1,
                                const float* __restrict__ Wo2, const float* __restrict__ bo2,
                                float* __restrict__ out) {
    int b = blockIdx.x;
    int j = threadIdx.x;   // 64
    __shared__ float qs[128];
    __shared__ float hr[64];
    qs[j] = g_qstar[b * 128 + j];
    qs[64 + j] = g_qstar[b * 128 + 64 + j];
    __syncthreads();
    float acc = bo1[j];
    const float* wr = Wo1 + j * 128;
#pragma unroll 4
    for (int k = 0; k < 128; k++) acc += qs[k] * wr[k];
    acc = fmaxf(acc, 0.f) * Wo2[j];
    hr[j] = acc;
    __syncthreads();
    for (int o = 32; o > 0; o >>= 1) {
        if (j < o) hr[j] += hr[j + o];
        __syncthreads();
    }
    if (j == 0) out[b] = hr[0] + bo2[0];
}

// ---------------- host launch ----------------
extern "C" void kernel_launch(void* const* d_in, const int* in_sizes, int n_in,
                              void* d_out, int out_size) {
    const float* x      = (const float*)d_in[0];
    const float* eattr  = (const float*)d_in[1];
    const float* W_in   = (const float*)d_in[2];
    const float* b_in   = (const float*)d_in[3];
    const float* W_e1   = (const float*)d_in[4];
    const float* b_e1   = (const float*)d_in[5];
    const float* W_e2   = (const float*)d_in[6];
    const float* b_e2   = (const float*)d_in[7];
    const float* b_conv = (const float*)d_in[8];
    const float* W_ih   = (const float*)d_in[9];
    const float* b_ih   = (const float*)d_in[10];
    const float* W_hh   = (const float*)d_in[11];
    const float* b_hh   = (const float*)d_in[12];
    const float* W_ih_l = (const float*)d_in[13];
    const float* b_ih_l = (const float*)d_in[14];
    const float* W_hh_l = (const float*)d_in[15];
    const float* b_hh_l = (const float*)d_in[16];
    const float* W_o1   = (const float*)d_in[17];
    const float* b_o1   = (const float*)d_in[18];
    const float* W_o2   = (const float*)d_in[19];
    const float* b_o2   = (const float*)d_in[20];
    const void*  eidx   = d_in[21];
    const void*  batch  = d_in[22];
    float* out = (float*)d_out;

    static bool attr_set = false;
    if (!attr_set) {
        cudaFuncSetAttribute(msg_gemm_kernel,
                             cudaFuncAttributeMaxDynamicSharedMemorySize, MSG_SMEM);
        attr_set = true;
    }

    dim3 mgrid((E_ + 127) / 128, KSPLIT);   // 157 x 5

    prep_kernel<<<(3 * N_ * D_ + 255) / 256, 256>>>(x, W_in, b_in, eattr, W_e1, b_e1,
                                                    W_e2, b_e2);             // 1
    convert_counts_kernel<<<(E_ + 255) / 256, 256>>>(eidx, batch);           // 2
    scan_ptr_kernel<<<1, 32>>>();                                            // 3

    msg_gemm_kernel<<<mgrid, 256, MSG_SMEM>>>(0);                            // 4 (profiled)
    gru_kernel<<<(N_ + 15) / 16, 192>>>(W_ih, b_ih, W_hh, b_hh, b_conv, 0);  // 5
    msg_gemm_kernel<<<mgrid, 256, MSG_SMEM>>>(1);                            // 6
    gru_kernel<<<(N_ + 15) / 16, 192>>>(W_ih, b_ih, W_hh, b_hh, b_conv, 1);  // 7
    msg_gemm_kernel<<<mgrid, 256, MSG_SMEM>>>(2);                            // 8
    gru_kernel<<<(N_ + 15) / 16, 192>>>(W_ih, b_ih, W_hh, b_hh, b_conv, 2);  // 9

    for (int it = 0; it < 3; it++) {
        lstm_kernel<<<(B_ + 7) / 8, 256>>>(W_ih_l, b_ih_l, W_hh_l, b_hh_l);
        attn_kernel<<<B_, 128>>>();
    }

    out_head_kernel<<<B_, 64>>>(W_o1, b_o1, W_o2, b_o2, out);
}

// round 15
// speedup vs baseline: 1.1327x; 1.0476x over previous
#include <cuda_runtime.h>
#include <cuda_fp16.h>
#include <math.h>
#include <stdint.h>

#define N_  10000
#define E_  20000
#define B_  400
#define ND_ 32
#define ED_ 16
#define D_  64
#define DD_ 4096   // D*D
#define KSPLIT 5   // K-chunks split across blockIdx.y (65 = 5*13)
#define KCPER 13

// ---------------- scratch (device globals; no cudaMalloc allowed) ----------------
__device__ float g_h[N_ * D_];            // node hidden / out (fp32)
__device__ __half g_rh[E_ * D_];          // edge MLP hidden, fp16
__device__ __half g_w3[65 * DD_];         // permuted W_e2 [k][f][d] (+ chunk 64 = b2^T)
__device__ float g_agg[3 * N_ * D_];      // scatter accumulators (one per iteration)
__device__ float g_cnt[N_];               // dst degree
__device__ int   g_src[E_], g_dst[E_], g_batch[N_];
__device__ int   g_gcnt[B_];
__device__ int   g_ptr[B_ + 1];
__device__ float g_qstar[B_ * 2 * D_];
__device__ float g_hl[B_ * D_];
__device__ float g_cl[B_ * D_];
__device__ float g_e[N_];                 // per-node attention logits / weights

__device__ __forceinline__ float sigm(float x) { return 1.f / (1.f + expf(-x)); }

__device__ __forceinline__ uint32_t smem_u32(const void* p) {
    uint32_t a;
    asm("{ .reg .u64 t; cvta.to.shared.u64 t, %1; cvt.u32.u64 %0, t; }" : "=r"(a) : "l"(p));
    return a;
}
__device__ __forceinline__ void cp16(uint32_t dst, const void* src) {
    asm volatile("cp.async.cg.shared.global [%0], [%1], 16;" :: "r"(dst), "l"(src));
}

// ---------------- prep: encoders + W3 build + zero init (launch #1) ----------------
__global__ void prep_kernel(const float* __restrict__ x,
                            const float* __restrict__ W_in, const float* __restrict__ b_in,
                            const float* __restrict__ ea,
                            const float* __restrict__ W_e1, const float* __restrict__ b_e1,
                            const float* __restrict__ W_e2, const float* __restrict__ b_e2) {
    int i = blockIdx.x * blockDim.x + threadIdx.x;
    if (i < N_ * D_) {
        int n = i >> 6, f = i & 63;
        float acc = b_in[f];
        const float* xr = x + n * ND_;
        const float* wr = W_in + f * ND_;
#pragma unroll
        for (int k = 0; k < ND_; k++) acc += xr[k] * wr[k];
        g_h[i] = fmaxf(acc, 0.f);
    } else if (i < N_ * D_ + E_ * D_) {
        int j = i - N_ * D_;
        int e = j >> 6, f = j & 63;
        float acc = b_e1[f];
        const float* er = ea + e * ED_;
        const float* wr = W_e1 + f * ED_;
#pragma unroll
        for (int k = 0; k < ED_; k++) acc += er[k] * wr[k];
        g_rh[j] = __float2half(fmaxf(acc, 0.f));
    }
    if (i < 65 * DD_) {
        int k = i >> 12, rem = i & 4095;
        int f = rem >> 6, d = rem & 63;
        float v = (k < 64) ? W_e2[(d * 64 + f) * 64 + k] : b_e2[d * 64 + f];
        g_w3[i] = __float2half(v);
    }
    if (i < 3 * N_ * D_) g_agg[i] = 0.f;
    if (i < N_) g_cnt[i] = 0.f;
    if (i < B_) g_gcnt[i] = 0;
    if (i < B_ * 2 * D_) g_qstar[i] = 0.f;
    if (i < B_ * D_) { g_hl[i] = 0.f; g_cl[i] = 0.f; }
}

// ---------------- convert + counts (detect inline) (launch #2) ----------------
__global__ void convert_counts_kernel(const void* ei, const void* ba) {
    int i = blockIdx.x * blockDim.x + threadIdx.x;
    int f0 = 1, f1 = 1;
    {
        const long long* p = (const long long*)ei;
#pragma unroll
        for (int t = 0; t < 8; t++) { long long v = p[t]; if (v < 0 || v >= N_) f0 = 0; }
#pragma unroll
        for (int t = 0; t < 8; t++) { long long v = p[2 * E_ / 2 - 8 + t]; if (v < 0 || v >= N_) f0 = 0; }
    }
    {
        const long long* p = (const long long*)ba;
#pragma unroll
        for (int t = 0; t < 8; t++) { long long v = p[t]; if (v < 0 || v >= B_) f1 = 0; }
#pragma unroll
        for (int t = 0; t < 8; t++) { long long v = p[N_ / 2 - 8 + t]; if (v < 0 || v >= B_) f1 = 0; }
    }
    if (i < E_) {
        int s, d;
        if (f0) {
            const long long* p = (const long long*)ei;
            s = (int)p[i]; d = (int)p[E_ + i];
        } else {
            const int* p = (const int*)ei;
            s = p[i]; d = p[E_ + i];
        }
        g_src[i] = s;
        g_dst[i] = d;
        atomicAdd(&g_cnt[d], 1.0f);
    }
    if (i < N_) {
        int b;
        if (f1) {
            const long long* p = (const long long*)ba;
            b = (int)p[i];
        } else {
            const int* p = (const int*)ba;
            b = p[i];
        }
        g_batch[i] = b;
        atomicAdd(&g_gcnt[b], 1);
    }
}

// ---------------- parallel prefix scan over 400 graph counts (launch #3) ----------------
__global__ void scan_ptr_kernel() {
    __shared__ int tmp[B_];
    int t = threadIdx.x;   // 512 threads
    if (t < B_) tmp[t] = g_gcnt[t];
    __syncthreads();
#pragma unroll
    for (int off = 1; off < B_; off <<= 1) {
        int v = 0;
        if (t < B_ && t >= off) v = tmp[t - off];
        __syncthreads();
        if (t < B_) tmp[t] += v;
        __syncthreads();
    }
    if (t < B_) g_ptr[t + 1] = tmp[t];
    if (t == 0) g_ptr[0] = 0;
}

// ============ fused NNConv message GEMM, K-split, register-A ============
// C[e,f] = sum_{k,d} r[e,k]*h[e,d]*W2[d*64+f,k] (+bias via virtual k=64).
// A-fragments of HS (gathered src h) loaded ONCE via ldmatrix; per chunk the
// fragment is scaled in registers by r[row,kc] (identical rounding to smem path).
// B chunks (8KB, L2-resident W3) double-buffered via cp.async.
#define EWP 72
#define HS_OFF 0                    // 128 x EWP halves = 9216
#define RS_OFF (128 * EWP)          // 9216 (width 68)
#define BS_OFF (RS_OFF + 128 * 68)  // 17920; two buffers of 64*EWP=4608 halves
#define MSG_SMEM ((BS_OFF + 2 * 64 * EWP) * 2)   // 54272 bytes

__device__ __forceinline__ void ldsm4(uint32_t addr, uint32_t* r) {
    asm volatile("ldmatrix.sync.aligned.m8n8.x4.shared.b16 {%0,%1,%2,%3}, [%4];"
                 : "=r"(r[0]), "=r"(r[1]), "=r"(r[2]), "=r"(r[3]) : "r"(addr));
}
__device__ __forceinline__ void mma_fp16(float* c, const uint32_t* a, uint32_t b0, uint32_t b1) {
    asm volatile(
        "mma.sync.aligned.m16n8k16.row.col.f32.f16.f16.f32 "
        "{%0,%1,%2,%3}, {%4,%5,%6,%7}, {%8,%9}, {%0,%1,%2,%3};"
        : "+f"(c[0]), "+f"(c[1]), "+f"(c[2]), "+f"(c[3])
        : "r"(a[0]), "r"(a[1]), "r"(a[2]), "r"(a[3]), "r"(b0), "r"(b1));
}

__global__ void __launch_bounds__(256) msg_gemm_kernel(int it) {
    extern __shared__ __half sm[];
    uint32_t sb = smem_u32(sm);
    int tid = threadIdx.x;
    int e0 = blockIdx.x * 128;
    int kc0 = blockIdx.y * KCPER;

    // stage HS (gathered src h -> fp16) and RS (r fp16, +1.0 at k=64)
    for (int i = tid; i < 128 * 32; i += 256) {
        int row = i >> 5, c2 = i & 31;
        int e = e0 + row;
        float2 hv = (e < E_) ? ((const float2*)&g_h[g_src[e] * 64])[c2] : make_float2(0.f, 0.f);
        *(__half2*)&sm[HS_OFF + row * EWP + c2 * 2] = __floats2half2_rn(hv.x, hv.y);
    }
    for (int i = tid; i < 128 * 32; i += 256) {
        int row = i >> 5, c2 = i & 31;
        int e = e0 + row;
        __half2 rv = (e < E_) ? *(const __half2*)&g_rh[e * 64 + c2 * 2]
                              : __half2half2(__float2half(0.f));
        *(__half2*)&sm[RS_OFF + row * 68 + c2 * 2] = rv;
    }
    if (tid < 128) sm[RS_OFF + tid * 68 + 64] = __float2half(1.0f);

    // prefetch BS chunk kc0 into buffer 0
    for (int i = tid; i < 512; i += 256) {
        int f = i >> 3, d8 = i & 7;
        cp16(sb + (uint32_t)(BS_OFF + f * EWP + d8 * 8) * 2,
             &g_w3[kc0 * DD_ + f * 64 + d8 * 8]);
    }
    asm volatile("cp.async.commit_group;" ::: "memory");
    __syncthreads();

    int w = tid >> 5, lane = tid & 31;
    int wm = w & 3, wn = w >> 2;
    int r8 = lane & 7, q = lane >> 3;
    int a_row = ((q & 1) ? 8 : 0) + r8;
    int a_col = (q >= 2) ? 8 : 0;
    int b_row = ((q >= 2) ? 8 : 0) + r8;
    int b_col = (q & 1) ? 8 : 0;
    int g = lane >> 2, qq = lane & 3;

    // A fragments of HS, loaded once (reused for all 13 chunks)
    uint32_t ah[4][2][4];
#pragma unroll
    for (int k0 = 0; k0 < 4; k0++)
#pragma unroll
        for (int t = 0; t < 2; t++) {
            uint32_t ad = sb + (uint32_t)(HS_OFF +
                (wm * 32 + t * 16 + a_row) * EWP + k0 * 16 + a_col) * 2;
            ldsm4(ad, ah[k0][t]);
        }

    float c[2][4][4];
#pragma unroll
    for (int t = 0; t < 2; t++)
#pragma unroll
        for (int n = 0; n < 4; n++)
#pragma unroll
            for (int j = 0; j < 4; j++) c[t][n][j] = 0.f;

#pragma unroll 1
    for (int kk = 0; kk < KCPER; kk++) {
        int kc = kc0 + kk;
        // stage next BS chunk (overwrites buffer used 2 chunks ago — guarded by
        // the end-of-chunk barrier of the previous iteration)
        if (kk + 1 < KCPER) {
            int kn = kc + 1;
            uint32_t bufn = (uint32_t)(BS_OFF + ((kk + 1) & 1) * 64 * EWP);
            for (int i = tid; i < 512; i += 256) {
                int f = i >> 3, d8 = i & 7;
                cp16(sb + (bufn + f * EWP + d8 * 8) * 2,
                     &g_w3[kn * DD_ + f * 64 + d8 * 8]);
            }
            asm volatile("cp.async.commit_group;" ::: "memory");
            asm volatile("cp.async.wait_group 1;" ::: "memory");
        } else {
            asm volatile("cp.async.wait_group 0;" ::: "memory");
        }
        __syncthreads();   // buf[kk&1] visible to all threads

        uint32_t buf = (uint32_t)(BS_OFF + (kk & 1) * 64 * EWP);

        // per-row r scalars for this chunk
        __half2 rk2[2][2];
#pragma unroll
        for (int t = 0; t < 2; t++) {
            int r0 = wm * 32 + t * 16 + g;
            rk2[t][0] = __half2half2(sm[RS_OFF + r0 * 68 + kc]);
            rk2[t][1] = __half2half2(sm[RS_OFF + (r0 + 8) * 68 + kc]);
        }

#pragma unroll
        for (int k0 = 0; k0 < 4; k0++) {
            uint32_t b[2][4];
#pragma unroll
            for (int p = 0; p < 2; p++) {
                uint32_t bd = sb + (buf + (wn * 32 + p * 16 + b_row) * EWP
                                   + k0 * 16 + b_col) * 2;
                ldsm4(bd, b[p]);
            }
#pragma unroll
            for (int t = 0; t < 2; t++) {
                uint32_t az[4];
                const __half2* ahh = (const __half2*)ah[k0][t];
                ((__half2*)az)[0] = __hmul2(ahh[0], rk2[t][0]);
                ((__half2*)az)[1] = __hmul2(ahh[1], rk2[t][1]);
                ((__half2*)az)[2] = __hmul2(ahh[2], rk2[t][0]);
                ((__half2*)az)[3] = __hmul2(ahh[3], rk2[t][1]);
#pragma unroll
                for (int n = 0; n < 4; n++) {
                    int p = n >> 1, s = (n & 1) * 2;
                    mma_fp16(c[t][n], az, b[p][s], b[p][s + 1]);
                }
            }
        }
        __syncthreads();   // all warps done with buf[kk&1] before it is restaged
    }

    // scatter partial sums to agg[dst]
    float* agg = &g_agg[(size_t)it * N_ * D_];
#pragma unroll
    for (int t = 0; t < 2; t++) {
        int ge0 = e0 + wm * 32 + t * 16 + g;
        int ge1 = ge0 + 8;
        int dst0 = (ge0 < E_) ? g_dst[ge0] : -1;
        int dst1 = (ge1 < E_) ? g_dst[ge1] : -1;
#pragma unroll
        for (int n = 0; n < 4; n++) {
            int col = wn * 32 + n * 8 + qq * 2;
            if (dst0 >= 0) {
                atomicAdd(&agg[dst0 * 64 + col], c[t][n][0]);
                atomicAdd(&agg[dst0 * 64 + col + 1], c[t][n][1]);
            }
            if (dst1 >= 0) {
                atomicAdd(&agg[dst1 * 64 + col], c[t][n][2]);
                atomicAdd(&agg[dst1 * 64 + col + 1], c[t][n][3]);
            }
        }
    }
}

// ---------------- GRU update over node tiles of 16 ----------------
__global__ void __launch_bounds__(192) gru_kernel(const float* __restrict__ Wih,
                                                  const float* __restrict__ bih,
                                                  const float* __restrict__ Whh,
                                                  const float* __restrict__ bhh,
                                                  const float* __restrict__ bconv,
                                                  int it) {
    __shared__ float Msm[16][64];
    __shared__ float Hsm[16][64];
    __shared__ float GI[16][192];
    __shared__ float GH[16][192];
    int n0 = blockIdx.x * 16;
    int tid = threadIdx.x;
    const float* agg = &g_agg[(size_t)it * N_ * D_];

    for (int idx = tid; idx < 16 * 64; idx += 192) {
        int m = idx >> 6, k = idx & 63;
        int n = n0 + m;
        if (n < N_) {
            float cdeg = fmaxf(g_cnt[n], 1.0f);
            Msm[m][k] = fmaxf(agg[n * 64 + k] / cdeg + bconv[k], 0.f);
            Hsm[m][k] = g_h[n * 64 + k];
        } else {
            Msm[m][k] = 0.f;
            Hsm[m][k] = 0.f;
        }
    }
    __syncthreads();

    float wih[64], whh[64];
    const float* wi = Wih + tid * 64;
    const float* wh = Whh + tid * 64;
#pragma unroll
    for (int k = 0; k < 64; k++) { wih[k] = __ldg(&wi[k]); whh[k] = __ldg(&wh[k]); }
    float bi = bih[tid], bh = bhh[tid];

#pragma unroll 4
    for (int m = 0; m < 16; m++) {
        float ai = bi, ah = bh;
#pragma unroll
        for (int k = 0; k < 64; k++) {
            ai += Msm[m][k] * wih[k];
            ah += Hsm[m][k] * whh[k];
        }
        GI[m][tid] = ai;
        GH[m][tid] = ah;
    }
    __syncthreads();

    for (int idx = tid; idx < 16 * 64; idx += 192) {
        int m = idx >> 6, f = idx & 63;
        int n = n0 + m;
        if (n >= N_) continue;
        float r = sigm(GI[m][f] + GH[m][f]);
        float z = sigm(GI[m][64 + f] + GH[m][64 + f]);
        float nn = tanhf(GI[m][128 + f] + r * GH[m][128 + f]);
        float hnew = (1.f - z) * nn + z * Hsm[m][f];
        g_h[n * 64 + f] = hnew;
    }
}

// ---------------- Set2Set LSTM cell (8 graphs per 256-thread block) ----------------
__global__ void lstm_kernel(const float* __restrict__ Wih, const float* __restrict__ bih,
                            const float* __restrict__ Whh, const float* __restrict__ bhh) {
    __shared__ float qs[8][128];
    __shared__ float hs[8][64];
    __shared__ float gsm[8][256];
    int b0 = blockIdx.x * 8;
    int tid = threadIdx.x;

    for (int idx = tid; idx < 8 * 128; idx += 256) {
        int g = idx >> 7, k = idx & 127;
        int b = b0 + g;
        qs[g][k] = (b < B_) ? g_qstar[b * 128 + k] : 0.f;
    }
    for (int idx = tid; idx < 8 * 64; idx += 256) {
        int g = idx >> 6, k = idx & 63;
        int b = b0 + g;
        hs[g][k] = (b < B_) ? g_hl[b * 64 + k] : 0.f;
    }
    __syncthreads();

    int j = tid;
    float acc[8];
    float bsum = bih[j] + bhh[j];
#pragma unroll
    for (int g = 0; g < 8; g++) acc[g] = bsum;
    const float* wi = Wih + j * 128;
    const float* wh = Whh + j * 64;
#pragma unroll 4
    for (int k = 0; k < 128; k++) {
        float w = __ldg(&wi[k]);
#pragma unroll
        for (int g = 0; g < 8; g++) acc[g] += qs[g][k] * w;
    }
#pragma unroll 4
    for (int k = 0; k < 64; k++) {
        float w = __ldg(&wh[k]);
#pragma unroll
        for (int g = 0; g < 8; g++) acc[g] += hs[g][k] * w;
    }
#pragma unroll
    for (int g = 0; g < 8; g++) gsm[g][j] = acc[g];
    __syncthreads();

    for (int idx = tid; idx < 8 * 64; idx += 256) {
        int g = idx >> 6, f = idx & 63;
        int b = b0 + g;
        if (b >= B_) continue;
        float ig = sigm(gsm[g][f]);
        float fg = sigm(gsm[g][64 + f]);
        float gg = tanhf(gsm[g][128 + f]);
        float og = sigm(gsm[g][192 + f]);
        float c = fg * g_cl[b * 64 + f] + ig * gg;
        float h = og * tanhf(c);
        g_cl[b * 64 + f] = c;
        g_hl[b * 64 + f] = h;
    }
}

// ---------------- attention (segment softmax + weighted sum) per graph ----------------
__global__ void attn_kernel() {
    int b = blockIdx.x;
    int tid = threadIdx.x;   // 128 threads
    __shared__ float qv[64];
    __shared__ float red[128];
    __shared__ float racc[2][64];
    if (tid < 64) qv[tid] = g_hl[b * 64 + tid];
    __syncthreads();

    int s = g_ptr[b], eend = g_ptr[b + 1];

    float lmax = -INFINITY;
    for (int n = s + tid; n < eend; n += 128) {
        const float4* hr = (const float4*)&g_h[n * 64];
        const float4* qq = (const float4*)qv;
        float d = 0.f;
#pragma unroll
        for (int k = 0; k < 16; k++) {
            float4 a = hr[k], c = qq[k];
            d += a.x * c.x + a.y * c.y + a.z * c.z + a.w * c.w;
        }
        g_e[n] = d;
        lmax = fmaxf(lmax, d);
    }
    red[tid] = lmax;
    __syncthreads();
    for (int o = 64; o > 0; o >>= 1) {
        if (tid < o) red[tid] = fmaxf(red[tid], red[tid + o]);
        __syncthreads();
    }
    float mmax = red[0];
    __syncthreads();

    float lsum = 0.f;
    for (int n = s + tid; n < eend; n += 128) {
        float a = expf(g_e[n] - mmax);
        g_e[n] = a;
        lsum += a;
    }
    red[tid] = lsum;
    __syncthreads();
    for (int o = 64; o > 0; o >>= 1) {
        if (tid < o) red[tid] += red[tid + o];
        __syncthreads();
    }
    float den = red[0];
    __syncthreads();

    {
        int par = tid >> 6;
        int col = tid & 63;
        float accr = 0.f;
        for (int n = s + par; n < eend; n += 2) accr += g_e[n] * g_h[n * 64 + col];
        racc[par][col] = accr;
    }
    __syncthreads();
    if (tid < 64) {
        float rv = racc[0][tid] + racc[1][tid];
        rv = (den > 0.f) ? rv / den : 0.f;
        g_qstar[b * 128 + tid] = qv[tid];
        g_qstar[b * 128 + 64 + tid] = rv;
    }
}

// ---------------- output head ----------------
__global__ void out_head_kernel(const float* __restrict__ Wo1, const float* __restrict__ bo1,
                                const float* __restrict__ Wo2, const float* __restrict__ bo2,
                                float* __restrict__ out) {
    int b = blockIdx.x;
    int j = threadIdx.x;   // 64
    __shared__ float qs[128];
    __shared__ float hr[64];
    qs[j] = g_qstar[b * 128 + j];
    qs[64 + j] = g_qstar[b * 128 + 64 + j];
    __syncthreads();
    float acc = bo1[j];
    const float* wr = Wo1 + j * 128;
#pragma unroll 4
    for (int k = 0; k < 128; k++) acc += qs[k] * wr[k];
    acc = fmaxf(acc, 0.f) * Wo2[j];
    hr[j] = acc;
    __syncthreads();
    for (int o = 32; o > 0; o >>= 1) {
        if (j < o) hr[j] += hr[j + o];
        __syncthreads();
    }
    if (j == 0) out[b] = hr[0] + bo2[0];
}

// ---------------- host launch ----------------
extern "C" void kernel_launch(void* const* d_in, const int* in_sizes, int n_in,
                              void* d_out, int out_size) {
    const float* x      = (const float*)d_in[0];
    const float* eattr  = (const float*)d_in[1];
    const float* W_in   = (const float*)d_in[2];
    const float* b_in   = (const float*)d_in[3];
    const float* W_e1   = (const float*)d_in[4];
    const float* b_e1   = (const float*)d_in[5];
    const float* W_e2   = (const float*)d_in[6];
    const float* b_e2   = (const float*)d_in[7];
    const float* b_conv = (const float*)d_in[8];
    const float* W_ih   = (const float*)d_in[9];
    const float* b_ih   = (const float*)d_in[10];
    const float* W_hh   = (const float*)d_in[11];
    const float* b_hh   = (const float*)d_in[12];
    const float* W_ih_l = (const float*)d_in[13];
    const float* b_ih_l = (const float*)d_in[14];
    const float* W_hh_l = (const float*)d_in[15];
    const float* b_hh_l = (const float*)d_in[16];
    const float* W_o1   = (const float*)d_in[17];
    const float* b_o1   = (const float*)d_in[18];
    const float* W_o2   = (const float*)d_in[19];
    const float* b_o2   = (const float*)d_in[20];
    const void*  eidx   = d_in[21];
    const void*  batch  = d_in[22];
    float* out = (float*)d_out;

    static bool attr_set = false;
    if (!attr_set) {
        cudaFuncSetAttribute(msg_gemm_kernel,
                             cudaFuncAttributeMaxDynamicSharedMemorySize, MSG_SMEM);
        attr_set = true;
    }

    dim3 mgrid((E_ + 127) / 128, KSPLIT);   // 157 x 5

    prep_kernel<<<(3 * N_ * D_ + 255) / 256, 256>>>(x, W_in, b_in, eattr, W_e1, b_e1,
                                                    W_e2, b_e2);             // 1
    convert_counts_kernel<<<(E_ + 255) / 256, 256>>>(eidx, batch);           // 2
    scan_ptr_kernel<<<1, 512>>>();                                           // 3

    msg_gemm_kernel<<<mgrid, 256, MSG_SMEM>>>(0);                            // 4 (profiled)
    gru_kernel<<<(N_ + 15) / 16, 192>>>(W_ih, b_ih, W_hh, b_hh, b_conv, 0);  // 5
    msg_gemm_kernel<<<mgrid, 256, MSG_SMEM>>>(1);                            // 6
    gru_kernel<<<(N_ + 15) / 16, 192>>>(W_ih, b_ih, W_hh, b_hh, b_conv, 1);  // 7
    msg_gemm_kernel<<<mgrid, 256, MSG_SMEM>>>(2);                            // 8
    gru_kernel<<<(N_ + 15) / 16, 192>>>(W_ih, b_ih, W_hh, b_hh, b_conv, 2);  // 9

    for (int it = 0; it < 3; it++) {
        lstm_kernel<<<(B_ + 7) / 8, 256>>>(W_ih_l, b_ih_l, W_hh_l, b_hh_l);
        attn_kernel<<<B_, 128>>>();
    }

    out_head_kernel<<<B_, 64>>>(W_o1, b_o1, W_o2, b_o2, out);
}